// round 10
// baseline (speedup 1.0000x reference)
#include <cuda_runtime.h>
#include <cuda_bf16.h>
#include <cstdint>

#define LRELU_ALPHA 0.2f
#define NROWS 200000
#define IN_F  256
#define OUT_F 128

#define RPB      48                      // rows per CTA (3 mma row-tiles)
#define THREADS  128                     // 4 warps
#define NBLK     ((NROWS + RPB - 1) / RPB)   // 4167

#define PSTRIDE  132                     // u32 (bf16-pairs) per row: 128 + 4 pad
#define AHI_OFF  512                     // after u vectors (512 floats)
#define ALO_OFF  (AHI_OFF + RPB * PSTRIDE)
#define SMEM_U32S (ALO_OFF + RPB * PSTRIDE)
#define SMEM_BYTES (SMEM_U32S * 4)       // 52736 B -> 4 CTAs/SM

__device__ float g_u[2 * IN_F];          // u_top | u_bot
// B fragments, fragment-ordered: [kstep s(16)][ntile(16)][lane(32)] -> {b0,b1}
__device__ uint2 g_Bhi[16 * 16 * 32];
__device__ uint2 g_Blo[16 * 16 * 32];

// ---------------------------------------------------------------------------
__device__ __forceinline__ uint32_t bfpair(float lo_elem, float hi_elem) {
    __nv_bfloat162 h = __floats2bfloat162_rn(lo_elem, hi_elem);
    return *reinterpret_cast<uint32_t*>(&h);
}

__device__ __forceinline__ float dot8(float4 x0, float4 x1, float4 y0, float4 y1) {
    float d = 0.f;
    d = fmaf(x0.x, y0.x, d); d = fmaf(x0.y, y0.y, d);
    d = fmaf(x0.z, y0.z, d); d = fmaf(x0.w, y0.w, d);
    d = fmaf(x1.x, y1.x, d); d = fmaf(x1.y, y1.y, d);
    d = fmaf(x1.z, y1.z, d); d = fmaf(x1.w, y1.w, d);
    return d;
}

#define MMA_BF16(d, a, b0v, b1v)                                               \
    asm volatile(                                                              \
        "mma.sync.aligned.m16n8k16.row.col.f32.bf16.bf16.f32 "                 \
        "{%0,%1,%2,%3}, {%4,%5,%6,%7}, {%8,%9}, {%0,%1,%2,%3};"                \
        : "+f"(d[0]), "+f"(d[1]), "+f"(d[2]), "+f"(d[3])                       \
        : "r"(a[0]), "r"(a[1]), "r"(a[2]), "r"(a[3]), "r"(b0v), "r"(b1v))

// ---------------------------------------------------------------------------
// Merged prep kernel: blocks 0..31 compute g_u (one warp per element);
// blocks 32..39 pack W into B-fragment order (each warp does 4 (s,nt) tasks).
// ---------------------------------------------------------------------------
__global__ void prep_kernel(const float* __restrict__ W,
                            const float* __restrict__ s) {
    const int warp = threadIdx.x >> 5;
    const int lane = threadIdx.x & 31;

    if (blockIdx.x < 32) {
        const int gw = blockIdx.x * 8 + warp;  // 0..255 (= i)
        const float* wrow = W + gw * OUT_F;
        float ut = 0.f, ub = 0.f;
#pragma unroll
        for (int jj = 0; jj < 4; ++jj) {
            int j = lane + jj * 32;
            float w = wrow[j];
            ut = fmaf(w, s[j], ut);
            ub = fmaf(w, s[OUT_F + j], ub);
        }
#pragma unroll
        for (int off = 16; off; off >>= 1) {
            ut += __shfl_xor_sync(0xffffffffu, ut, off);
            ub += __shfl_xor_sync(0xffffffffu, ub, off);
        }
        if (lane == 0) {
            g_u[gw] = ut;
            g_u[IN_F + gw] = ub;
        }
    } else {
        const int wtask0 = (blockIdx.x - 32) * 8 + warp;  // 0..63
        const int g = lane >> 2, t = lane & 3;
#pragma unroll
        for (int j = 0; j < 4; ++j) {
            int task = wtask0 + 64 * j;        // 0..255
            int sstep = task >> 4;             // 0..15
            int nt = task & 15;                // 0..15
            int n = nt * 8 + g;
            uint32_t hv[2], lv[2];
#pragma unroll
            for (int rg = 0; rg < 2; ++rg) {
                int k = sstep * 16 + rg * 8 + 2 * t;
                float w0 = W[k * OUT_F + n];
                float w1 = W[(k + 1) * OUT_F + n];
                float h0 = __bfloat162float(__float2bfloat16_rn(w0));
                float h1 = __bfloat162float(__float2bfloat16_rn(w1));
                hv[rg] = bfpair(h0, h1);
                lv[rg] = bfpair(w0 - h0, w1 - h1);
            }
            int idx = (sstep * 16 + nt) * 32 + lane;
            g_Bhi[idx] = make_uint2(hv[0], hv[1]);
            g_Blo[idx] = make_uint2(lv[0], lv[1]);
        }
    }
}

// ---------------------------------------------------------------------------
// Fused kernel: logits -> softmax -> mix (bf16 hi/lo frag layout in smem)
//               -> HMMA GEMM (mix @ W) -> out
// Phase 1 is software-pipelined over the 6 row-pairs per warp.
// ---------------------------------------------------------------------------
__global__ __launch_bounds__(THREADS, 4)
void fused_attention_kernel(const float* __restrict__ T,
                            const float* __restrict__ O1,
                            const float* __restrict__ O2,
                            float* __restrict__ out) {
    extern __shared__ char smem_raw[];
    uint32_t* s32 = reinterpret_cast<uint32_t*>(smem_raw);
    float* s_u = reinterpret_cast<float*>(smem_raw);
    uint32_t* smA_hi = s32 + AHI_OFF;
    uint32_t* smA_lo = s32 + ALO_OFF;

    const int tid  = threadIdx.x;
    const int lane = tid & 31;
    const int w    = tid >> 5;    // 0..3
    const int row0 = blockIdx.x * RPB;

    for (int i = tid; i < 2 * IN_F; i += THREADS) s_u[i] = g_u[i];
    __syncthreads();

    // ---------------- Phase 1 (pipelined): 12 rows per warp, 6 pairs --------
    {
        const float4* up = reinterpret_cast<const float4*>(s_u) + lane * 2;
        const float4 ut0 = up[0], ut1 = up[1];
        const float4* bp = reinterpret_cast<const float4*>(s_u + IN_F) + lane * 2;
        const float4 ub0 = bp[0], ub1 = bp[1];

        float4 buf0[6][2], buf1[6][2];

        // load row pair (rr, rr+1); rr is the pair start, even, 0..10
        auto load_pair = [&](int rr, float4 (&v)[6][2]) {
            const int rA = w * 12 + rr;
            long long gA = (long long)(row0 + rA);
            long long gB = gA + 1;
            if (gA >= NROWS) gA = NROWS - 1;
            if (gB >= NROWS) gB = NROWS - 1;
            const float4* tA = reinterpret_cast<const float4*>(T  + gA * IN_F) + lane * 2;
            const float4* aA = reinterpret_cast<const float4*>(O1 + gA * IN_F) + lane * 2;
            const float4* bA = reinterpret_cast<const float4*>(O2 + gA * IN_F) + lane * 2;
            const float4* tB = reinterpret_cast<const float4*>(T  + gB * IN_F) + lane * 2;
            const float4* aB = reinterpret_cast<const float4*>(O1 + gB * IN_F) + lane * 2;
            const float4* bB = reinterpret_cast<const float4*>(O2 + gB * IN_F) + lane * 2;
            v[0][0] = tA[0]; v[0][1] = tA[1];
            v[1][0] = aA[0]; v[1][1] = aA[1];
            v[2][0] = bA[0]; v[2][1] = bA[1];
            v[3][0] = tB[0]; v[3][1] = tB[1];
            v[4][0] = aB[0]; v[4][1] = aB[1];
            v[5][0] = bB[0]; v[5][1] = bB[1];
        };

        // process one resident pair (rows rr, rr+1 of this warp)
        auto process_pair = [&](int rr, float4 (&v)[6][2]) {
            float dtt0 = dot8(v[0][0], v[0][1], ut0, ut1);
            float dtb0 = dot8(v[0][0], v[0][1], ub0, ub1);
            float d1_0 = dot8(v[1][0], v[1][1], ub0, ub1);
            float d2_0 = dot8(v[2][0], v[2][1], ub0, ub1);
            float dtt1 = dot8(v[3][0], v[3][1], ut0, ut1);
            float dtb1 = dot8(v[3][0], v[3][1], ub0, ub1);
            float d1_1 = dot8(v[4][0], v[4][1], ub0, ub1);
            float d2_1 = dot8(v[5][0], v[5][1], ub0, ub1);
#pragma unroll
            for (int off = 16; off; off >>= 1) {
                dtt0 += __shfl_xor_sync(0xffffffffu, dtt0, off);
                dtb0 += __shfl_xor_sync(0xffffffffu, dtb0, off);
                d1_0 += __shfl_xor_sync(0xffffffffu, d1_0, off);
                d2_0 += __shfl_xor_sync(0xffffffffu, d2_0, off);
                dtt1 += __shfl_xor_sync(0xffffffffu, dtt1, off);
                dtb1 += __shfl_xor_sync(0xffffffffu, dtb1, off);
                d1_1 += __shfl_xor_sync(0xffffffffu, d1_1, off);
                d2_1 += __shfl_xor_sync(0xffffffffu, d2_1, off);
            }
#pragma unroll
            for (int h = 0; h < 2; ++h) {
                const int r = w * 12 + rr + h;
                float dtt = h ? dtt1 : dtt0;
                float dtb = h ? dtb1 : dtb0;
                float d1v = h ? d1_1 : d1_0;
                float d2v = h ? d2_1 : d2_0;
                float4 x0 = v[3 * h + 0][0], x1 = v[3 * h + 0][1];
                float4 y0 = v[3 * h + 1][0], y1 = v[3 * h + 1][1];
                float4 z0 = v[3 * h + 2][0], z1 = v[3 * h + 2][1];

                float e0 = dtt + dtb, e1 = dtt + d1v, e2 = dtt + d2v;
                e0 = e0 > 0.f ? e0 : LRELU_ALPHA * e0;
                e1 = e1 > 0.f ? e1 : LRELU_ALPHA * e1;
                e2 = e2 > 0.f ? e2 : LRELU_ALPHA * e2;
                float m = fmaxf(e0, fmaxf(e1, e2));
                float w0 = __expf(e0 - m), w1 = __expf(e1 - m), w2 = __expf(e2 - m);
                float inv = 1.f / (w0 + w1 + w2);
                w0 *= inv; w1 *= inv; w2 *= inv;

                float mx[8];
                mx[0] = fmaf(w0, x0.x, fmaf(w1, y0.x, w2 * z0.x));
                mx[1] = fmaf(w0, x0.y, fmaf(w1, y0.y, w2 * z0.y));
                mx[2] = fmaf(w0, x0.z, fmaf(w1, y0.z, w2 * z0.z));
                mx[3] = fmaf(w0, x0.w, fmaf(w1, y0.w, w2 * z0.w));
                mx[4] = fmaf(w0, x1.x, fmaf(w1, y1.x, w2 * z1.x));
                mx[5] = fmaf(w0, x1.y, fmaf(w1, y1.y, w2 * z1.y));
                mx[6] = fmaf(w0, x1.z, fmaf(w1, y1.z, w2 * z1.z));
                mx[7] = fmaf(w0, x1.w, fmaf(w1, y1.w, w2 * z1.w));

                float hf[8], lf[8];
#pragma unroll
                for (int i = 0; i < 8; ++i) {
                    hf[i] = __bfloat162float(__float2bfloat16_rn(mx[i]));
                    lf[i] = mx[i] - hf[i];
                }
                uint4 vh = make_uint4(bfpair(hf[0], hf[1]), bfpair(hf[2], hf[3]),
                                      bfpair(hf[4], hf[5]), bfpair(hf[6], hf[7]));
                uint4 vl = make_uint4(bfpair(lf[0], lf[1]), bfpair(lf[2], lf[3]),
                                      bfpair(lf[4], lf[5]), bfpair(lf[6], lf[7]));
                *reinterpret_cast<uint4*>(smA_hi + r * PSTRIDE + lane * 4) = vh;
                *reinterpret_cast<uint4*>(smA_lo + r * PSTRIDE + lane * 4) = vl;
            }
        };

        // 6 pairs: starts 0,2,4,6,8,10. Ping-pong two register buffers.
        load_pair(0, buf0);
#pragma unroll
        for (int it = 0; it < 3; ++it) {
            load_pair(4 * it + 2, buf1);            // prefetch odd-slot pair
            process_pair(4 * it, buf0);
            if (it < 2) load_pair(4 * it + 4, buf0); // prefetch next even-slot pair
            process_pair(4 * it + 2, buf1);
        }
    }
    __syncthreads();

    // ---------------- Phase 2: out[48x128] = mix @ W via HMMA ---------------
    // warp w owns cols [32w, 32w+32): 4 n-tiles; 3 row-tiles of 16.
    {
        const int g = lane >> 2;       // 0..7
        const int t = lane & 3;        // 0..3

        float acc[3][4][4];
#pragma unroll
        for (int r = 0; r < 3; ++r)
#pragma unroll
            for (int c = 0; c < 4; ++c)
#pragma unroll
                for (int i = 0; i < 4; ++i) acc[r][c][i] = 0.f;

#pragma unroll 1
        for (int s = 0; s < 16; ++s) {
            uint32_t ah[3][4], al[3][4];
#pragma unroll
            for (int r = 0; r < 3; ++r) {
                int base = (16 * r + g) * PSTRIDE + 8 * s + t;
                ah[r][0] = smA_hi[base];
                ah[r][1] = smA_hi[base + 8 * PSTRIDE];
                ah[r][2] = smA_hi[base + 4];
                ah[r][3] = smA_hi[base + 8 * PSTRIDE + 4];
                al[r][0] = smA_lo[base];
                al[r][1] = smA_lo[base + 8 * PSTRIDE];
                al[r][2] = smA_lo[base + 4];
                al[r][3] = smA_lo[base + 8 * PSTRIDE + 4];
            }
#pragma unroll
            for (int c = 0; c < 4; ++c) {
                int nt = w * 4 + c;
                uint2 bh = __ldg(&g_Bhi[(s * 16 + nt) * 32 + lane]);
                uint2 bl = __ldg(&g_Blo[(s * 16 + nt) * 32 + lane]);
#pragma unroll
                for (int r = 0; r < 3; ++r) {
                    MMA_BF16(acc[r][c], ah[r], bh.x, bh.y);
                    MMA_BF16(acc[r][c], al[r], bh.x, bh.y);
                    MMA_BF16(acc[r][c], ah[r], bl.x, bl.y);
                }
            }
        }

        // epilogue: d0,d1 -> (row 16r+g, cols 2t,2t+1); d2,d3 -> row +8
#pragma unroll
        for (int r = 0; r < 3; ++r) {
            const long long rowA = (long long)(row0 + 16 * r + g);
            const long long rowB = rowA + 8;
            const bool vA = rowA < NROWS;
            const bool vB = rowB < NROWS;
#pragma unroll
            for (int c = 0; c < 4; ++c) {
                const int col = 32 * w + 8 * c + 2 * t;
                if (vA) {
                    float2 v0 = make_float2(acc[r][c][0], acc[r][c][1]);
                    *reinterpret_cast<float2*>(out + rowA * OUT_F + col) = v0;
                }
                if (vB) {
                    float2 v1 = make_float2(acc[r][c][2], acc[r][c][3]);
                    *reinterpret_cast<float2*>(out + rowB * OUT_F + col) = v1;
                }
            }
        }
    }
}

// ---------------------------------------------------------------------------
extern "C" void kernel_launch(void* const* d_in, const int* in_sizes, int n_in,
                              void* d_out, int out_size) {
    const float* T  = (const float*)d_in[0];
    const float* O1 = (const float*)d_in[1];
    const float* O2 = (const float*)d_in[2];
    const float* W  = (const float*)d_in[3];
    const float* s  = (const float*)d_in[4];
    float* out = (float*)d_out;

    cudaFuncSetAttribute(fused_attention_kernel,
                         cudaFuncAttributeMaxDynamicSharedMemorySize, SMEM_BYTES);

    prep_kernel<<<40, 256>>>(W, s);
    fused_attention_kernel<<<NBLK, THREADS, SMEM_BYTES>>>(T, O1, O2, out);
}

// round 11
// speedup vs baseline: 1.1987x; 1.1987x over previous
#include <cuda_runtime.h>
#include <cuda_bf16.h>
#include <cstdint>

#define LRELU_ALPHA 0.2f
#define NROWS 200000
#define IN_F  256
#define OUT_F 128

#define RPB      48                      // rows per CTA (3 mma row-tiles)
#define THREADS  256                     // 8 warps
#define NBLK     ((NROWS + RPB - 1) / RPB)   // 4167

#define PSTRIDE  132                     // u32 (bf16-pairs) per row: 128 + 4 pad
#define AHI_OFF  512                     // after u vectors (512 floats)
#define ALO_OFF  (AHI_OFF + RPB * PSTRIDE)
#define SMEM_U32S (ALO_OFF + RPB * PSTRIDE)
#define SMEM_BYTES (SMEM_U32S * 4)       // 52736 B -> 3 CTAs/SM (reg-capped)

__device__ float g_u[2 * IN_F];          // u_top | u_bot
// B fragments, fragment-ordered: [kstep s(16)][ntile(16)][lane(32)] -> {b0,b1}
__device__ uint2 g_Bhi[16 * 16 * 32];
__device__ uint2 g_Blo[16 * 16 * 32];

// ---------------------------------------------------------------------------
__device__ __forceinline__ uint32_t bfpair(float lo_elem, float hi_elem) {
    __nv_bfloat162 h = __floats2bfloat162_rn(lo_elem, hi_elem);
    return *reinterpret_cast<uint32_t*>(&h);
}

__device__ __forceinline__ float dot8(float4 x0, float4 x1, float4 y0, float4 y1) {
    float d = 0.f;
    d = fmaf(x0.x, y0.x, d); d = fmaf(x0.y, y0.y, d);
    d = fmaf(x0.z, y0.z, d); d = fmaf(x0.w, y0.w, d);
    d = fmaf(x1.x, y1.x, d); d = fmaf(x1.y, y1.y, d);
    d = fmaf(x1.z, y1.z, d); d = fmaf(x1.w, y1.w, d);
    return d;
}

#define MMA_BF16(d, a, b0v, b1v)                                               \
    asm volatile(                                                              \
        "mma.sync.aligned.m16n8k16.row.col.f32.bf16.bf16.f32 "                 \
        "{%0,%1,%2,%3}, {%4,%5,%6,%7}, {%8,%9}, {%0,%1,%2,%3};"                \
        : "+f"(d[0]), "+f"(d[1]), "+f"(d[2]), "+f"(d[3])                       \
        : "r"(a[0]), "r"(a[1]), "r"(a[2]), "r"(a[3]), "r"(b0v), "r"(b1v))

// ---------------------------------------------------------------------------
// Merged prep kernel: blocks 0..31 compute g_u (one warp per element);
// blocks 32..39 pack W into B-fragment order (each warp does 4 (s,nt) tasks).
// ---------------------------------------------------------------------------
__global__ void prep_kernel(const float* __restrict__ W,
                            const float* __restrict__ s) {
    const int warp = threadIdx.x >> 5;
    const int lane = threadIdx.x & 31;

    if (blockIdx.x < 32) {
        const int gw = blockIdx.x * 8 + warp;  // 0..255 (= i)
        const float* wrow = W + gw * OUT_F;
        float ut = 0.f, ub = 0.f;
#pragma unroll
        for (int jj = 0; jj < 4; ++jj) {
            int j = lane + jj * 32;
            float w = wrow[j];
            ut = fmaf(w, s[j], ut);
            ub = fmaf(w, s[OUT_F + j], ub);
        }
#pragma unroll
        for (int off = 16; off; off >>= 1) {
            ut += __shfl_xor_sync(0xffffffffu, ut, off);
            ub += __shfl_xor_sync(0xffffffffu, ub, off);
        }
        if (lane == 0) {
            g_u[gw] = ut;
            g_u[IN_F + gw] = ub;
        }
    } else {
        const int wtask0 = (blockIdx.x - 32) * 8 + warp;  // 0..63
        const int g = lane >> 2, t = lane & 3;
#pragma unroll
        for (int j = 0; j < 4; ++j) {
            int task = wtask0 + 64 * j;        // 0..255
            int sstep = task >> 4;             // 0..15
            int nt = task & 15;                // 0..15
            int n = nt * 8 + g;
            uint32_t hv[2], lv[2];
#pragma unroll
            for (int rg = 0; rg < 2; ++rg) {
                int k = sstep * 16 + rg * 8 + 2 * t;
                float w0 = W[k * OUT_F + n];
                float w1 = W[(k + 1) * OUT_F + n];
                float h0 = __bfloat162float(__float2bfloat16_rn(w0));
                float h1 = __bfloat162float(__float2bfloat16_rn(w1));
                hv[rg] = bfpair(h0, h1);
                lv[rg] = bfpair(w0 - h0, w1 - h1);
            }
            int idx = (sstep * 16 + nt) * 32 + lane;
            g_Bhi[idx] = make_uint2(hv[0], hv[1]);
            g_Blo[idx] = make_uint2(lv[0], lv[1]);
        }
    }
}

// ---------------------------------------------------------------------------
// Fused kernel: logits -> softmax -> mix (bf16 hi/lo frag layout in smem)
//               -> HMMA GEMM (mix @ W) -> out
// 8 warps/CTA, 3 CTAs/SM (24 warps/SM) for latency hiding; single-row
// phase-1 processing keeps regs under the 85/thread cap.
// ---------------------------------------------------------------------------
__global__ __launch_bounds__(THREADS, 3)
void fused_attention_kernel(const float* __restrict__ T,
                            const float* __restrict__ O1,
                            const float* __restrict__ O2,
                            float* __restrict__ out) {
    extern __shared__ char smem_raw[];
    uint32_t* s32 = reinterpret_cast<uint32_t*>(smem_raw);
    float* s_u = reinterpret_cast<float*>(smem_raw);
    uint32_t* smA_hi = s32 + AHI_OFF;
    uint32_t* smA_lo = s32 + ALO_OFF;

    const int tid  = threadIdx.x;
    const int lane = tid & 31;
    const int w    = tid >> 5;    // 0..7
    const int row0 = blockIdx.x * RPB;

    for (int i = tid; i < 2 * IN_F; i += THREADS) s_u[i] = g_u[i];
    __syncthreads();

    // ---------------- Phase 1: 6 rows per warp, one row at a time -----------
    {
        const float4* up = reinterpret_cast<const float4*>(s_u) + lane * 2;
        const float4 ut0 = up[0], ut1 = up[1];
        const float4* bp = reinterpret_cast<const float4*>(s_u + IN_F) + lane * 2;
        const float4 ub0 = bp[0], ub1 = bp[1];

#pragma unroll 1
        for (int rr = 0; rr < 6; ++rr) {
            const int r = w * 6 + rr;
            long long g = (long long)(row0 + r);
            if (g >= NROWS) g = NROWS - 1;

            const float4* tp = reinterpret_cast<const float4*>(T  + g * IN_F) + lane * 2;
            const float4* ap = reinterpret_cast<const float4*>(O1 + g * IN_F) + lane * 2;
            const float4* zp = reinterpret_cast<const float4*>(O2 + g * IN_F) + lane * 2;
            float4 x0 = tp[0], x1 = tp[1];
            float4 y0 = ap[0], y1 = ap[1];
            float4 z0 = zp[0], z1 = zp[1];

            float dtt = dot8(x0, x1, ut0, ut1);
            float dtb = dot8(x0, x1, ub0, ub1);
            float d1v = dot8(y0, y1, ub0, ub1);
            float d2v = dot8(z0, z1, ub0, ub1);
#pragma unroll
            for (int off = 16; off; off >>= 1) {
                dtt += __shfl_xor_sync(0xffffffffu, dtt, off);
                dtb += __shfl_xor_sync(0xffffffffu, dtb, off);
                d1v += __shfl_xor_sync(0xffffffffu, d1v, off);
                d2v += __shfl_xor_sync(0xffffffffu, d2v, off);
            }

            float e0 = dtt + dtb, e1 = dtt + d1v, e2 = dtt + d2v;
            e0 = e0 > 0.f ? e0 : LRELU_ALPHA * e0;
            e1 = e1 > 0.f ? e1 : LRELU_ALPHA * e1;
            e2 = e2 > 0.f ? e2 : LRELU_ALPHA * e2;
            float m = fmaxf(e0, fmaxf(e1, e2));
            float w0 = __expf(e0 - m), w1 = __expf(e1 - m), w2 = __expf(e2 - m);
            float inv = 1.f / (w0 + w1 + w2);
            w0 *= inv; w1 *= inv; w2 *= inv;

            float mx[8];
            mx[0] = fmaf(w0, x0.x, fmaf(w1, y0.x, w2 * z0.x));
            mx[1] = fmaf(w0, x0.y, fmaf(w1, y0.y, w2 * z0.y));
            mx[2] = fmaf(w0, x0.z, fmaf(w1, y0.z, w2 * z0.z));
            mx[3] = fmaf(w0, x0.w, fmaf(w1, y0.w, w2 * z0.w));
            mx[4] = fmaf(w0, x1.x, fmaf(w1, y1.x, w2 * z1.x));
            mx[5] = fmaf(w0, x1.y, fmaf(w1, y1.y, w2 * z1.y));
            mx[6] = fmaf(w0, x1.z, fmaf(w1, y1.z, w2 * z1.z));
            mx[7] = fmaf(w0, x1.w, fmaf(w1, y1.w, w2 * z1.w));

            float hf[8], lf[8];
#pragma unroll
            for (int i = 0; i < 8; ++i) {
                hf[i] = __bfloat162float(__float2bfloat16_rn(mx[i]));
                lf[i] = mx[i] - hf[i];
            }
            uint4 vh = make_uint4(bfpair(hf[0], hf[1]), bfpair(hf[2], hf[3]),
                                  bfpair(hf[4], hf[5]), bfpair(hf[6], hf[7]));
            uint4 vl = make_uint4(bfpair(lf[0], lf[1]), bfpair(lf[2], lf[3]),
                                  bfpair(lf[4], lf[5]), bfpair(lf[6], lf[7]));
            *reinterpret_cast<uint4*>(smA_hi + r * PSTRIDE + lane * 4) = vh;
            *reinterpret_cast<uint4*>(smA_lo + r * PSTRIDE + lane * 4) = vl;
        }
    }
    __syncthreads();

    // ---------------- Phase 2: out[48x128] = mix @ W via HMMA ---------------
    // warp w owns n-tiles {2w, 2w+1} (cols 16w..16w+15); 3 row-tiles of 16.
    {
        const int g = lane >> 2;       // 0..7
        const int t = lane & 3;        // 0..3

        float acc[3][2][4];
#pragma unroll
        for (int r = 0; r < 3; ++r)
#pragma unroll
            for (int c = 0; c < 2; ++c)
#pragma unroll
                for (int i = 0; i < 4; ++i) acc[r][c][i] = 0.f;

#pragma unroll 1
        for (int s = 0; s < 16; ++s) {
            uint32_t ah[3][4], al[3][4];
#pragma unroll
            for (int r = 0; r < 3; ++r) {
                int base = (16 * r + g) * PSTRIDE + 8 * s + t;
                ah[r][0] = smA_hi[base];
                ah[r][1] = smA_hi[base + 8 * PSTRIDE];
                ah[r][2] = smA_hi[base + 4];
                ah[r][3] = smA_hi[base + 8 * PSTRIDE + 4];
                al[r][0] = smA_lo[base];
                al[r][1] = smA_lo[base + 8 * PSTRIDE];
                al[r][2] = smA_lo[base + 4];
                al[r][3] = smA_lo[base + 8 * PSTRIDE + 4];
            }
#pragma unroll
            for (int c = 0; c < 2; ++c) {
                int nt = 2 * w + c;
                uint2 bh = __ldg(&g_Bhi[(s * 16 + nt) * 32 + lane]);
                uint2 bl = __ldg(&g_Blo[(s * 16 + nt) * 32 + lane]);
#pragma unroll
                for (int r = 0; r < 3; ++r) {
                    MMA_BF16(acc[r][c], ah[r], bh.x, bh.y);
                    MMA_BF16(acc[r][c], al[r], bh.x, bh.y);
                    MMA_BF16(acc[r][c], ah[r], bl.x, bl.y);
                }
            }
        }

        // epilogue: d0,d1 -> (row 16r+g, cols 2t,2t+1); d2,d3 -> row +8
#pragma unroll
        for (int r = 0; r < 3; ++r) {
            const long long rowA = (long long)(row0 + 16 * r + g);
            const long long rowB = rowA + 8;
            const bool vA = rowA < NROWS;
            const bool vB = rowB < NROWS;
#pragma unroll
            for (int c = 0; c < 2; ++c) {
                const int col = 8 * (2 * w + c) + 2 * t;
                if (vA) {
                    float2 v0 = make_float2(acc[r][c][0], acc[r][c][1]);
                    *reinterpret_cast<float2*>(out + rowA * OUT_F + col) = v0;
                }
                if (vB) {
                    float2 v1 = make_float2(acc[r][c][2], acc[r][c][3]);
                    *reinterpret_cast<float2*>(out + rowB * OUT_F + col) = v1;
                }
            }
        }
    }
}

// ---------------------------------------------------------------------------
extern "C" void kernel_launch(void* const* d_in, const int* in_sizes, int n_in,
                              void* d_out, int out_size) {
    const float* T  = (const float*)d_in[0];
    const float* O1 = (const float*)d_in[1];
    const float* O2 = (const float*)d_in[2];
    const float* W  = (const float*)d_in[3];
    const float* s  = (const float*)d_in[4];
    float* out = (float*)d_out;

    cudaFuncSetAttribute(fused_attention_kernel,
                         cudaFuncAttributeMaxDynamicSharedMemorySize, SMEM_BYTES);

    prep_kernel<<<40, 256>>>(W, s);
    fused_attention_kernel<<<NBLK, THREADS, SMEM_BYTES>>>(T, O1, O2, out);
}